// round 15
// baseline (speedup 1.0000x reference)
#include <cuda_runtime.h>
#include <cuda_bf16.h>
#include <cstdint>

#define TDIM   1024
#define NSTEP  1023
#define IN_DIM 35

// output layout: coeff [256][1023][5] | mean [256][1023][5][32] | var [256][1023][5]
#define MEANBASE 1309440
#define VARBASE  43211520

// ---------------- device scratch (allocation-free) ----------------
__device__ float g_H[(size_t)NSTEP * 256 * 256];            // fp32 h, [t][k][b] (MDN)
__device__ __nv_bfloat16 g_HbT[(size_t)NSTEP * 256 * 256];  // bf16 h, [t][b][k] (recurrence)
__device__ float g_GX[(size_t)NSTEP * 1024 * 256];          // x-projection [t][j][b]
__device__ float g_W1t[256 * 112];
__device__ float g_W2t[112 * 112];
__device__ float g_W3t[112 * 176];
__device__ float g_b1p[112];
__device__ float g_b2p[112];
__device__ float g_b3p[176];
__device__ unsigned g_done[128];   // [bg][jg] steps completed

// ---------------- prep ----------------
__global__ void prep_w(const float* __restrict__ W1, const float* __restrict__ b1,
                       const float* __restrict__ W2, const float* __restrict__ b2,
                       const float* __restrict__ W3, const float* __restrict__ b3)
{
    int id = blockIdx.x * blockDim.x + threadIdx.x;
    int stride = gridDim.x * blockDim.x;
    if (id < 128) g_done[id] = 0u;
    for (int i = id; i < 256 * 112; i += stride) {
        int k = i / 112, m = i - k * 112;
        g_W1t[i] = (m < 100) ? W1[m * 256 + k] : 0.f;
    }
    for (int i = id; i < 112 * 112; i += stride) {
        int k = i / 112, m = i - k * 112;
        g_W2t[i] = (k < 100 && m < 100) ? W2[m * 100 + k] : 0.f;
    }
    for (int i = id; i < 112 * 176; i += stride) {
        int k = i / 176, m = i - k * 176;
        g_W3t[i] = (k < 100 && m < 170) ? W3[m * 100 + k] : 0.f;
    }
    for (int i = id; i < 112; i += stride) {
        g_b1p[i] = (i < 100) ? b1[i] : 0.f;
        g_b2p[i] = (i < 100) ? b2[i] : 0.f;
    }
    for (int i = id; i < 176; i += stride) g_b3p[i] = (i < 170) ? b3[i] : 0.f;
}

// ---------------- x-projection ----------------
__global__ void __launch_bounds__(256)
xproj_kernel(const float* __restrict__ x, const float* __restrict__ W_ih)
{
    __shared__ float Ws[IN_DIM][64];
    __shared__ float xs[IN_DIM][64];
    const int tid = threadIdx.x;
    const int t  = blockIdx.x;
    const int jt = blockIdx.y;
    const int bt = blockIdx.z;

    for (int i = tid; i < 64 * IN_DIM; i += 256) {
        int m = i / IN_DIM, c = i - m * IN_DIM;
        Ws[c][m] = W_ih[(jt * 64 + m) * IN_DIM + c];
    }
    for (int i = tid; i < 64 * IN_DIM; i += 256) {
        int n = i / IN_DIM, c = i - n * IN_DIM;
        xs[c][n] = x[((size_t)(bt * 64 + n) * TDIM + t) * IN_DIM + c];
    }
    __syncthreads();

    const int tm = tid >> 4;
    const int tb = tid & 15;
    float acc[4][4];
#pragma unroll
    for (int i = 0; i < 4; ++i)
#pragma unroll
        for (int j = 0; j < 4; ++j) acc[i][j] = 0.f;
#pragma unroll 5
    for (int c = 0; c < IN_DIM; ++c) {
        float4 a  = *reinterpret_cast<const float4*>(&Ws[c][tm << 2]);
        float4 b4 = *reinterpret_cast<const float4*>(&xs[c][tb << 2]);
        float av[4] = {a.x, a.y, a.z, a.w};
        float bv[4] = {b4.x, b4.y, b4.z, b4.w};
#pragma unroll
        for (int i = 0; i < 4; ++i)
#pragma unroll
            for (int j = 0; j < 4; ++j) acc[i][j] = fmaf(av[i], bv[j], acc[i][j]);
    }
    float* dst = g_GX + (size_t)t * 262144 + (size_t)(jt * 64 + (tm << 2)) * 256
                 + bt * 64 + (tb << 2);
#pragma unroll
    for (int i = 0; i < 4; ++i)
        *reinterpret_cast<float4*>(dst + (size_t)i * 256) =
            make_float4(acc[i][0], acc[i][1], acc[i][2], acc[i][3]);
}

__device__ __forceinline__ float sigf(float v)     { return 1.f / (1.f + __expf(-v)); }
__device__ __forceinline__ float tanhfast(float v) { return 1.f - 2.f / (__expf(2.f * v) + 1.f); }
__device__ __forceinline__ float ldcg1(const float* p) {
    float v;
    asm volatile("ld.global.cg.f32 %0,[%1];" : "=f"(v) : "l"(p));
    return v;
}
__device__ __forceinline__ uint32_t ldcgu(const void* p) {
    uint32_t v;
    asm volatile("ld.global.cg.u32 %0,[%1];" : "=r"(v) : "l"(p));
    return v;
}
__device__ __forceinline__ uint32_t smem_u32(const void* p) {
    uint32_t a;
    asm("{ .reg .u64 t; cvta.to.shared.u64 t, %1; cvt.u32.u64 %0, t; }" : "=r"(a) : "l"(p));
    return a;
}
__device__ __forceinline__ void waitflag(const unsigned* f, unsigned tgt) {
    unsigned v;
    for (;;) {
        asm volatile("ld.acquire.gpu.global.u32 %0,[%1];" : "=r"(v) : "l"(f));
        if (v >= tgt) break;
        __nanosleep(20);
    }
}

// ---------------- mma helpers ----------------
__device__ __forceinline__ void ldsm4(uint32_t* r, uint32_t a) {
    asm volatile("ldmatrix.sync.aligned.m8n8.x4.shared.b16 {%0,%1,%2,%3}, [%4];"
        : "=r"(r[0]), "=r"(r[1]), "=r"(r[2]), "=r"(r[3]) : "r"(a));
}
__device__ __forceinline__ void mma_bf16(float* d, const uint32_t* a, const uint32_t* b) {
    asm volatile("mma.sync.aligned.m16n8k16.row.col.f32.bf16.bf16.f32 "
        "{%0,%1,%2,%3}, {%4,%5,%6,%7}, {%8,%9}, {%0,%1,%2,%3};"
        : "+f"(d[0]), "+f"(d[1]), "+f"(d[2]), "+f"(d[3])
        : "r"(a[0]), "r"(a[1]), "r"(a[2]), "r"(a[3]), "r"(b[0]), "r"(b[1]));
}
__device__ __forceinline__ uint32_t pack_bf(__nv_bfloat16 lo, __nv_bfloat16 hi) {
    return (uint32_t)__bfloat16_as_ushort(lo) | ((uint32_t)__bfloat16_as_ushort(hi) << 16);
}
__device__ __forceinline__ void split2(float v, __nv_bfloat16& a, __nv_bfloat16& b) {
    a = __float2bfloat16(v);
    b = __float2bfloat16(v - __bfloat162float(a));
}

// ---------------- persistent LSTM (HMMA, flag-pipelined, no global barrier) ----------------
// grid 148 (>=128 exit): jg = blockIdx>>3 (16 hid-tiles of 16), bg = blockIdx&7 (8 batch-tiles of 32)
// M=64 gate rows (m = jh*4 + gate), N=32, K=256. 512 threads = 16 warps (4 mt x 4 nt).
#define WSP_OFF  0                    // bf16 [2][m=64][k pad 264]
#define WSP_SPL  33792
#define WGS_OFF  67584                // per-warp f32 [16][10] (640B each)
#define LSTM_SMEM_BYTES 78336

__global__ void __launch_bounds__(512, 1)
lstm_kernel(const float* __restrict__ W_hh,
            const float* __restrict__ b_ih, const float* __restrict__ b_hh)
{
    extern __shared__ char smc[];
    if (blockIdx.x >= 128) return;
    const uint32_t sbase = smem_u32(smc);

    const int tid = threadIdx.x;
    const int bg  = blockIdx.x & 7;
    const int jg  = blockIdx.x >> 3;

    // one-time W staging: m = jh*4 + gate, 2 exact bf16 splits, [m=64][k pad 264]
    {
        int m = tid >> 3, kc = tid & 7;
        int j = (m & 3) * 256 + (jg << 4) + (m >> 2);      // gate*256 + jh_full
        const float* wrow = W_hh + (size_t)j * 256;
#pragma unroll
        for (int q = 0; q < 4; ++q) {
            int k0 = kc * 32 + q * 8;
            float4 u0 = *reinterpret_cast<const float4*>(wrow + k0);
            float4 u1 = *reinterpret_cast<const float4*>(wrow + k0 + 4);
            __nv_bfloat16 a[8], b[8];
            split2(u0.x, a[0], b[0]); split2(u0.y, a[1], b[1]);
            split2(u0.z, a[2], b[2]); split2(u0.w, a[3], b[3]);
            split2(u1.x, a[4], b[4]); split2(u1.y, a[5], b[5]);
            split2(u1.z, a[6], b[6]); split2(u1.w, a[7], b[7]);
            uint4 qa = make_uint4(pack_bf(a[0], a[1]), pack_bf(a[2], a[3]),
                                  pack_bf(a[4], a[5]), pack_bf(a[6], a[7]));
            uint4 qb = make_uint4(pack_bf(b[0], b[1]), pack_bf(b[2], b[3]),
                                  pack_bf(b[4], b[5]), pack_bf(b[6], b[7]));
            *reinterpret_cast<uint4*>(smc + WSP_OFF + m * 528 + k0 * 2) = qa;
            *reinterpret_cast<uint4*>(smc + WSP_OFF + WSP_SPL + m * 528 + k0 * 2) = qb;
        }
    }
    __syncthreads();

    // roles
    const int wid  = tid >> 5;
    const int lane = tid & 31;
    const int mt = wid >> 2, nt = wid & 3;
    const uint32_t aA0 = sbase + WSP_OFF +
        (uint32_t)(mt * 16 + (lane & 15)) * 528 + ((lane >> 4) * 16);
    const uint32_t aA1 = aA0 + WSP_SPL;
    float* wg = reinterpret_cast<float*>(smc + WGS_OFF + wid * 640);

    // B-fragment coords: n = bg*32 + nt*8 + lane/4 ; k0 = (lane%4)*2
    const int bn  = (bg << 5) + nt * 8 + (lane >> 2);
    const int bk0 = (lane & 3) << 1;
    const unsigned* flg = g_done + (bg << 4);

    // combine cell
    const int jhl = lane >> 3, nl = lane & 7;
    const int jh_full = (jg << 4) + mt * 4 + jhl;
    const int bcol = (bg << 5) + nt * 8 + nl;
    const size_t gxoff = (size_t)jh_full * 256 + bcol;

    float bias_r[4];
#pragma unroll
    for (int g = 0; g < 4; ++g) {
        int j = g * 256 + jh_full;
        bias_r[g] = b_ih[j] + b_hh[j];
    }
    float creg = 0.f;

    for (int t = 0; t < NSTEP; ++t) {
        // early gx loads
        const float* gp = g_GX + (size_t)t * 262144 + gxoff;
        float gxi = ldcg1(gp);
        float gxf = ldcg1(gp + 65536);
        float gxg = ldcg1(gp + 131072);
        float gxo = ldcg1(gp + 196608);

        float gi = 0.f, gf = 0.f, gg = 0.f, go = 0.f;
        if (t > 0) {
            const char* hbase = reinterpret_cast<const char*>(
                g_HbT + (size_t)(t - 1) * 65536 + (size_t)bn * 256 + bk0);
            // depth-3 prefetch ring over 16 k-chunks (chunk kk = producer jg=kk)
            uint32_t pre[3][2];
            waitflag(flg + 0, (unsigned)t);
            pre[0][0] = ldcgu(hbase);       pre[0][1] = ldcgu(hbase + 16);
            waitflag(flg + 1, (unsigned)t);
            pre[1][0] = ldcgu(hbase + 32);  pre[1][1] = ldcgu(hbase + 48);
            waitflag(flg + 2, (unsigned)t);
            pre[2][0] = ldcgu(hbase + 64);  pre[2][1] = ldcgu(hbase + 80);

            float d[4] = {0.f, 0.f, 0.f, 0.f};
#pragma unroll
            for (int kk = 0; kk < 16; ++kk) {
                int slot = kk % 3;
                uint32_t b0[2] = { pre[slot][0], pre[slot][1] };
                if (kk + 3 < 16) {
                    waitflag(flg + kk + 3, (unsigned)t);
                    pre[slot][0] = ldcgu(hbase + (kk + 3) * 32);
                    pre[slot][1] = ldcgu(hbase + (kk + 3) * 32 + 16);
                }
                uint32_t a0[4], a1[4];
                ldsm4(a0, aA0 + kk * 32);
                ldsm4(a1, aA1 + kk * 32);
                mma_bf16(d, a0, b0);
                mma_bf16(d, a1, b0);
            }
            // dump D tile into per-warp patch [16][10]
            int r0 = lane >> 2, c2 = (lane & 3) << 1;
            *reinterpret_cast<float2*>(wg + r0 * 10 + c2) = make_float2(d[0], d[1]);
            *reinterpret_cast<float2*>(wg + (r0 + 8) * 10 + c2) = make_float2(d[2], d[3]);
            __syncwarp();
            gi = wg[(jhl * 4 + 0) * 10 + nl];
            gf = wg[(jhl * 4 + 1) * 10 + nl];
            gg = wg[(jhl * 4 + 2) * 10 + nl];
            go = wg[(jhl * 4 + 3) * 10 + nl];
        }
        // combine (c in register)
        {
            float iv = sigf(gxi + bias_r[0] + gi);
            float fv = sigf(gxf + bias_r[1] + gf);
            float gv = tanhfast(gxg + bias_r[2] + gg);
            float ov = sigf(gxo + bias_r[3] + go);
            float cv = fv * creg + iv * gv;
            creg = cv;
            float hv = ov * tanhfast(cv);
            g_H  [(size_t)t * 65536 + (size_t)jh_full * 256 + bcol] = hv;
            g_HbT[(size_t)t * 65536 + (size_t)bcol * 256 + jh_full] = __float2bfloat16(hv);
        }
        __syncthreads();
        if (tid == 0) {
            __threadfence();
            asm volatile("st.release.gpu.global.u32 [%0],%1;"
                         :: "l"(g_done + (bg << 4) + jg), "r"((unsigned)(t + 1)) : "memory");
        }
    }
}

// ---------------- MDN head ----------------
__device__ __forceinline__ void mdn_gemm(
    const float* __restrict__ At, int ldA, int mTiles, int K,
    const float* __restrict__ Bs, int ldb, float* __restrict__ Cs,
    const float* __restrict__ biasv, bool relu)
{
    for (int tile = threadIdx.x; tile < mTiles * 8; tile += blockDim.x) {
        int tm = tile % mTiles, tb = tile / mTiles;
        int m = tm << 2;
        const float* Ap = At + m;
        const float* Bp = Bs + (tb << 2);
        float acc[4][4];
#pragma unroll
        for (int i = 0; i < 4; ++i)
#pragma unroll
            for (int j = 0; j < 4; ++j) acc[i][j] = 0.f;
#pragma unroll 4
        for (int k = 0; k < K; ++k) {
            float4 a  = *reinterpret_cast<const float4*>(Ap + k * ldA);
            float4 b4 = *reinterpret_cast<const float4*>(Bp + k * ldb);
            float av[4] = {a.x, a.y, a.z, a.w};
            float bv[4] = {b4.x, b4.y, b4.z, b4.w};
#pragma unroll
            for (int i = 0; i < 4; ++i)
#pragma unroll
                for (int j = 0; j < 4; ++j) acc[i][j] = fmaf(av[i], bv[j], acc[i][j]);
        }
#pragma unroll
        for (int i = 0; i < 4; ++i) {
            float bv = biasv[m + i];
            float4 r = make_float4(acc[i][0] + bv, acc[i][1] + bv,
                                   acc[i][2] + bv, acc[i][3] + bv);
            if (relu) { r.x = fmaxf(r.x, 0.f); r.y = fmaxf(r.y, 0.f);
                        r.z = fmaxf(r.z, 0.f); r.w = fmaxf(r.w, 0.f); }
            *reinterpret_cast<float4*>(&Cs[(m + i) * 36 + (tb << 2)]) = r;
        }
    }
}

#define MDN_SMEM_BYTES ((256*32 + 112*36 + 176*36) * 4)

__global__ void __launch_bounds__(256, 2)
mdn_kernel(float* __restrict__ out)
{
    extern __shared__ float sm[];
    float* hT = sm;                 // [256][32], reused as h2 [112][36]
    float* h1 = hT + 256 * 32;      // [112][36]
    float* o3 = h1 + 112 * 36;      // [176][36]

    const int tid = threadIdx.x;
    const int t   = blockIdx.x >> 3;
    const int bg  = blockIdx.x & 7;

    const float* hp = g_H + (size_t)t * 65536 + (bg << 5);
    for (int i = tid; i < 2048; i += 256) {
        int k = i >> 3, nb = i & 7;
        float4 v = *reinterpret_cast<const float4*>(hp + (size_t)k * 256 + (nb << 2));
        *reinterpret_cast<float4*>(&hT[k * 32 + (nb << 2)]) = v;
    }
    __syncthreads();

    mdn_gemm(g_W1t, 112, 28, 256, hT, 32, h1, g_b1p, true);
    __syncthreads();
    mdn_gemm(g_W2t, 112, 28, 112, h1, 36, hT, g_b2p, true);   // h2 -> hT (reuse)
    __syncthreads();
    mdn_gemm(g_W3t, 176, 44, 112, hT, 36, o3, g_b3p, false);
    __syncthreads();

    if (tid < 32) {
        int n = tid;
        size_t r = (size_t)((bg << 5) + n) * NSTEP + t;
        float l[5];
        float mx = -1e30f;
#pragma unroll
        for (int k = 0; k < 5; ++k) { l[k] = o3[k * 36 + n]; mx = fmaxf(mx, l[k]); }
        float s = 0.f;
#pragma unroll
        for (int k = 0; k < 5; ++k) { l[k] = __expf(l[k] - mx); s += l[k]; }
        float inv = 1.f / s;
#pragma unroll
        for (int k = 0; k < 5; ++k) out[r * 5 + k] = l[k] * inv;
#pragma unroll
        for (int k = 0; k < 5; ++k)
            out[VARBASE + r * 5 + k] = __expf(o3[(5 + k) * 36 + n]);
    }
    for (int i = tid; i < 5120; i += 256) {
        int n = i / 160, j = i - n * 160;
        size_t r = (size_t)((bg << 5) + n) * NSTEP + t;
        out[MEANBASE + r * 160 + j] = o3[(10 + j) * 36 + n];
    }
}

extern "C" void kernel_launch(void* const* d_in, const int* in_sizes, int n_in,
                              void* d_out, int out_size)
{
    const float* x    = (const float*)d_in[0];
    const float* W_ih = (const float*)d_in[1];
    const float* W_hh = (const float*)d_in[2];
    const float* b_ih = (const float*)d_in[3];
    const float* b_hh = (const float*)d_in[4];
    const float* W1   = (const float*)d_in[5];
    const float* b1   = (const float*)d_in[6];
    const float* W2   = (const float*)d_in[7];
    const float* b2   = (const float*)d_in[8];
    const float* W3   = (const float*)d_in[9];
    const float* b3   = (const float*)d_in[10];
    float* out = (float*)d_out;

    cudaFuncSetAttribute(lstm_kernel, cudaFuncAttributeMaxDynamicSharedMemorySize, LSTM_SMEM_BYTES);
    cudaFuncSetAttribute(mdn_kernel,  cudaFuncAttributeMaxDynamicSharedMemorySize, MDN_SMEM_BYTES);

    prep_w<<<128, 256>>>(W1, b1, W2, b2, W3, b3);
    xproj_kernel<<<dim3(NSTEP, 16, 4), 256>>>(x, W_ih);
    lstm_kernel<<<148, 512, LSTM_SMEM_BYTES>>>(W_hh, b_ih, b_hh);
    mdn_kernel<<<NSTEP * 8, 256, MDN_SMEM_BYTES>>>(out);
}

// round 16
// speedup vs baseline: 1.7111x; 1.7111x over previous
#include <cuda_runtime.h>
#include <cuda_bf16.h>
#include <cstdint>

#define TDIM   1024
#define NSTEP  1023
#define IN_DIM 35

// output layout: coeff [256][1023][5] | mean [256][1023][5][32] | var [256][1023][5]
#define MEANBASE 1309440
#define VARBASE  43211520

// ---------------- device scratch (allocation-free) ----------------
__device__ float g_H[(size_t)NSTEP * 256 * 256];            // fp32 h, [t][k][b] (MDN)
__device__ __nv_bfloat16 g_Hb[(size_t)NSTEP * 256 * 256];   // bf16 h, [t][k][b] (recurrence)
__device__ float g_GX[(size_t)NSTEP * 1024 * 256];          // x-projection [t][j][b]
__device__ float g_W1t[256 * 112];
__device__ float g_W2t[112 * 112];
__device__ float g_W3t[112 * 176];
__device__ float g_b1p[112];
__device__ float g_b2p[112];
__device__ float g_b3p[176];
__device__ unsigned g_flag[128];   // [bg][jg] steps completed (per-producer)

// ---------------- prep ----------------
__global__ void prep_w(const float* __restrict__ W1, const float* __restrict__ b1,
                       const float* __restrict__ W2, const float* __restrict__ b2,
                       const float* __restrict__ W3, const float* __restrict__ b3)
{
    int id = blockIdx.x * blockDim.x + threadIdx.x;
    int stride = gridDim.x * blockDim.x;
    if (id < 128) g_flag[id] = 0u;
    for (int i = id; i < 256 * 112; i += stride) {
        int k = i / 112, m = i - k * 112;
        g_W1t[i] = (m < 100) ? W1[m * 256 + k] : 0.f;
    }
    for (int i = id; i < 112 * 112; i += stride) {
        int k = i / 112, m = i - k * 112;
        g_W2t[i] = (k < 100 && m < 100) ? W2[m * 100 + k] : 0.f;
    }
    for (int i = id; i < 112 * 176; i += stride) {
        int k = i / 176, m = i - k * 176;
        g_W3t[i] = (k < 100 && m < 170) ? W3[m * 100 + k] : 0.f;
    }
    for (int i = id; i < 112; i += stride) {
        g_b1p[i] = (i < 100) ? b1[i] : 0.f;
        g_b2p[i] = (i < 100) ? b2[i] : 0.f;
    }
    for (int i = id; i < 176; i += stride) g_b3p[i] = (i < 170) ? b3[i] : 0.f;
}

// ---------------- x-projection ----------------
__global__ void __launch_bounds__(256)
xproj_kernel(const float* __restrict__ x, const float* __restrict__ W_ih)
{
    __shared__ float Ws[IN_DIM][64];
    __shared__ float xs[IN_DIM][64];
    const int tid = threadIdx.x;
    const int t  = blockIdx.x;
    const int jt = blockIdx.y;
    const int bt = blockIdx.z;

    for (int i = tid; i < 64 * IN_DIM; i += 256) {
        int m = i / IN_DIM, c = i - m * IN_DIM;
        Ws[c][m] = W_ih[(jt * 64 + m) * IN_DIM + c];
    }
    for (int i = tid; i < 64 * IN_DIM; i += 256) {
        int n = i / IN_DIM, c = i - n * IN_DIM;
        xs[c][n] = x[((size_t)(bt * 64 + n) * TDIM + t) * IN_DIM + c];
    }
    __syncthreads();

    const int tm = tid >> 4;
    const int tb = tid & 15;
    float acc[4][4];
#pragma unroll
    for (int i = 0; i < 4; ++i)
#pragma unroll
        for (int j = 0; j < 4; ++j) acc[i][j] = 0.f;
#pragma unroll 5
    for (int c = 0; c < IN_DIM; ++c) {
        float4 a  = *reinterpret_cast<const float4*>(&Ws[c][tm << 2]);
        float4 b4 = *reinterpret_cast<const float4*>(&xs[c][tb << 2]);
        float av[4] = {a.x, a.y, a.z, a.w};
        float bv[4] = {b4.x, b4.y, b4.z, b4.w};
#pragma unroll
        for (int i = 0; i < 4; ++i)
#pragma unroll
            for (int j = 0; j < 4; ++j) acc[i][j] = fmaf(av[i], bv[j], acc[i][j]);
    }
    float* dst = g_GX + (size_t)t * 262144 + (size_t)(jt * 64 + (tm << 2)) * 256
                 + bt * 64 + (tb << 2);
#pragma unroll
    for (int i = 0; i < 4; ++i)
        *reinterpret_cast<float4*>(dst + (size_t)i * 256) =
            make_float4(acc[i][0], acc[i][1], acc[i][2], acc[i][3]);
}

__device__ __forceinline__ float sigf(float v)     { return 1.f / (1.f + __expf(-v)); }
__device__ __forceinline__ float tanhfast(float v) { return 1.f - 2.f / (__expf(2.f * v) + 1.f); }
__device__ __forceinline__ float ldcg1(const float* p) {
    float v;
    asm volatile("ld.global.cg.f32 %0,[%1];" : "=f"(v) : "l"(p));
    return v;
}
__device__ __forceinline__ uint2 ldcg2u(const void* p) {
    uint2 v;
    asm volatile("ld.global.cg.v2.u32 {%0,%1},[%2];" : "=r"(v.x), "=r"(v.y) : "l"(p));
    return v;
}
__device__ __forceinline__ uint32_t smem_u32(const void* p) {
    uint32_t a;
    asm("{ .reg .u64 t; cvta.to.shared.u64 t, %1; cvt.u32.u64 %0, t; }" : "=r"(a) : "l"(p));
    return a;
}

// ---------------- mma helpers ----------------
__device__ __forceinline__ void ldsm4(uint32_t* r, uint32_t a) {
    asm volatile("ldmatrix.sync.aligned.m8n8.x4.shared.b16 {%0,%1,%2,%3}, [%4];"
        : "=r"(r[0]), "=r"(r[1]), "=r"(r[2]), "=r"(r[3]) : "r"(a));
}
__device__ __forceinline__ void ldsm2t(uint32_t* r, uint32_t a) {
    asm volatile("ldmatrix.sync.aligned.m8n8.x2.trans.shared.b16 {%0,%1}, [%2];"
        : "=r"(r[0]), "=r"(r[1]) : "r"(a));
}
__device__ __forceinline__ void mma_bf16(float* d, const uint32_t* a, const uint32_t* b) {
    asm volatile("mma.sync.aligned.m16n8k16.row.col.f32.bf16.bf16.f32 "
        "{%0,%1,%2,%3}, {%4,%5,%6,%7}, {%8,%9}, {%0,%1,%2,%3};"
        : "+f"(d[0]), "+f"(d[1]), "+f"(d[2]), "+f"(d[3])
        : "r"(a[0]), "r"(a[1]), "r"(a[2]), "r"(a[3]), "r"(b[0]), "r"(b[1]));
}
__device__ __forceinline__ uint32_t pack_bf(__nv_bfloat16 lo, __nv_bfloat16 hi) {
    return (uint32_t)__bfloat16_as_ushort(lo) | ((uint32_t)__bfloat16_as_ushort(hi) << 16);
}

// ---------------- persistent LSTM (HMMA, single bf16 product, flag barrier) ----------------
// grid 148 (>=128 exit): jg = blockIdx>>3 (16 hid-tiles of 16), bg = blockIdx&7 (8 batch-tiles of 32)
// M=64 gate rows (m = jh*4 + gate), N=32, K=256. 512 threads = 16 warps (4 mt x 4 nt).
#define WSP_OFF  0                    // bf16 [m=64][k pad 264]
#define HSP_OFF  33792                // bf16 [k=256][n pad 40]
#define WGS_OFF  54272                // per-warp f32 [16][10] (640B each)
#define LSTM_SMEM_BYTES 120000        // padded: force 1 block/SM

__global__ void __launch_bounds__(512, 1)
lstm_kernel(const float* __restrict__ W_hh,
            const float* __restrict__ b_ih, const float* __restrict__ b_hh)
{
    extern __shared__ char smc[];
    if (blockIdx.x >= 128) return;
    const uint32_t sbase = smem_u32(smc);

    const int tid = threadIdx.x;
    const int bg  = blockIdx.x & 7;
    const int jg  = blockIdx.x >> 3;

    // one-time W staging: m = jh*4 + gate, single bf16, [m=64][k pad 264]
    {
        int m = tid >> 3, kc = tid & 7;
        int j = (m & 3) * 256 + (jg << 4) + (m >> 2);      // gate*256 + jh_full
        const float* wrow = W_hh + (size_t)j * 256;
#pragma unroll
        for (int q = 0; q < 4; ++q) {
            int k0 = kc * 32 + q * 8;
            float4 u0 = *reinterpret_cast<const float4*>(wrow + k0);
            float4 u1 = *reinterpret_cast<const float4*>(wrow + k0 + 4);
            uint4 qa = make_uint4(
                pack_bf(__float2bfloat16(u0.x), __float2bfloat16(u0.y)),
                pack_bf(__float2bfloat16(u0.z), __float2bfloat16(u0.w)),
                pack_bf(__float2bfloat16(u1.x), __float2bfloat16(u1.y)),
                pack_bf(__float2bfloat16(u1.z), __float2bfloat16(u1.w)));
            *reinterpret_cast<uint4*>(smc + WSP_OFF + m * 528 + k0 * 2) = qa;
        }
    }
    __syncthreads();

    // roles
    const int wid  = tid >> 5;
    const int lane = tid & 31;
    const int mt = wid >> 2, nt = wid & 3;
    const uint32_t aA0 = sbase + WSP_OFF +
        (uint32_t)(mt * 16 + (lane & 15)) * 528 + ((lane >> 4) * 16);
    const uint32_t aB0 = sbase + HSP_OFF + (uint32_t)(lane & 15) * 80 + nt * 16;
    float* wg = reinterpret_cast<float*>(smc + WGS_OFF + wid * 640);

    // combine cell: jh_full = jg*16 + mt*4 + jhl ; b = bg*32 + nt*8 + nl
    const int jhl = lane >> 3, nl = lane & 7;
    const int jh_full = (jg << 4) + mt * 4 + jhl;
    const int bcol = (bg << 5) + nt * 8 + nl;
    const size_t gxoff = (size_t)jh_full * 256 + bcol;
    const size_t hoff  = (size_t)jh_full * 256 + bcol;

    float bias_r[4];
#pragma unroll
    for (int g = 0; g < 4; ++g) {
        int j = g * 256 + jh_full;
        bias_r[g] = b_ih[j] + b_hh[j];
    }
    float creg = 0.f;

    // staging role
    const int sn4 = (tid & 7) << 2;
    const int skb = tid >> 3;

    for (int t = 0; t < NSTEP; ++t) {
        // early gx loads
        const float* gp = g_GX + (size_t)t * 262144 + gxoff;
        float gxi = ldcg1(gp);
        float gxf = ldcg1(gp + 65536);
        float gxg = ldcg1(gp + 131072);
        float gxo = ldcg1(gp + 196608);

        // stage h(t-1): bf16 copy g_Hb -> smem [k][n pad 40]
        if (t > 0) {
            const __nv_bfloat16* hb = g_Hb + (size_t)(t - 1) * 65536 + (bg << 5) + sn4;
#pragma unroll
            for (int i = 0; i < 4; ++i) {
                int k = skb + (i << 6);
                uint2 v = ldcg2u(hb + (size_t)k * 256);
                *reinterpret_cast<uint2*>(smc + HSP_OFF + k * 80 + sn4 * 2) = v;
            }
        }
        __syncthreads();

        // tensor GEMM (single product) + in-warp combine
        float gi = 0.f, gf = 0.f, gg = 0.f, go = 0.f;
        if (t > 0) {
            float d[4] = {0.f, 0.f, 0.f, 0.f};
#pragma unroll
            for (int kk = 0; kk < 16; ++kk) {
                uint32_t a0[4], b0[2];
                ldsm4(a0, aA0 + kk * 32);
                ldsm2t(b0, aB0 + kk * 1280);
                mma_bf16(d, a0, b0);
            }
            int r0 = lane >> 2, c2 = (lane & 3) << 1;
            *reinterpret_cast<float2*>(wg + r0 * 10 + c2) = make_float2(d[0], d[1]);
            *reinterpret_cast<float2*>(wg + (r0 + 8) * 10 + c2) = make_float2(d[2], d[3]);
            __syncwarp();
            gi = wg[(jhl * 4 + 0) * 10 + nl];
            gf = wg[(jhl * 4 + 1) * 10 + nl];
            gg = wg[(jhl * 4 + 2) * 10 + nl];
            go = wg[(jhl * 4 + 3) * 10 + nl];
        }
        // combine (c in register)
        {
            float iv = sigf(gxi + bias_r[0] + gi);
            float fv = sigf(gxf + bias_r[1] + gf);
            float gv = tanhfast(gxg + bias_r[2] + gg);
            float ov = sigf(gxo + bias_r[3] + go);
            float cv = fv * creg + iv * gv;
            creg = cv;
            float hv = ov * tanhfast(cv);
            g_H [(size_t)t * 65536 + hoff] = hv;
            g_Hb[(size_t)t * 65536 + hoff] = __float2bfloat16(hv);
        }
        __syncthreads();

        // barrier: per-producer flag stores + 16 parallel pollers (no atomic chain)
        if (tid == 0) {
            __threadfence();
            asm volatile("st.release.gpu.global.u32 [%0],%1;"
                         :: "l"(g_flag + (bg << 4) + jg), "r"((unsigned)(t + 1)) : "memory");
        }
        if (tid < 16) {
            const unsigned* f = g_flag + (bg << 4) + tid;
            unsigned v;
            for (;;) {
                asm volatile("ld.acquire.gpu.global.u32 %0,[%1];" : "=r"(v) : "l"(f));
                if (v >= (unsigned)(t + 1)) break;
                __nanosleep(20);
            }
        }
        __syncthreads();
    }
}

// ---------------- MDN head ----------------
__device__ __forceinline__ void mdn_gemm(
    const float* __restrict__ At, int ldA, int mTiles, int K,
    const float* __restrict__ Bs, int ldb, float* __restrict__ Cs,
    const float* __restrict__ biasv, bool relu)
{
    for (int tile = threadIdx.x; tile < mTiles * 8; tile += blockDim.x) {
        int tm = tile % mTiles, tb = tile / mTiles;
        int m = tm << 2;
        const float* Ap = At + m;
        const float* Bp = Bs + (tb << 2);
        float acc[4][4];
#pragma unroll
        for (int i = 0; i < 4; ++i)
#pragma unroll
            for (int j = 0; j < 4; ++j) acc[i][j] = 0.f;
#pragma unroll 8
        for (int k = 0; k < K; ++k) {
            float4 a  = *reinterpret_cast<const float4*>(Ap + k * ldA);
            float4 b4 = *reinterpret_cast<const float4*>(Bp + k * ldb);
            float av[4] = {a.x, a.y, a.z, a.w};
            float bv[4] = {b4.x, b4.y, b4.z, b4.w};
#pragma unroll
            for (int i = 0; i < 4; ++i)
#pragma unroll
                for (int j = 0; j < 4; ++j) acc[i][j] = fmaf(av[i], bv[j], acc[i][j]);
        }
#pragma unroll
        for (int i = 0; i < 4; ++i) {
            float bv = biasv[m + i];
            float4 r = make_float4(acc[i][0] + bv, acc[i][1] + bv,
                                   acc[i][2] + bv, acc[i][3] + bv);
            if (relu) { r.x = fmaxf(r.x, 0.f); r.y = fmaxf(r.y, 0.f);
                        r.z = fmaxf(r.z, 0.f); r.w = fmaxf(r.w, 0.f); }
            *reinterpret_cast<float4*>(&Cs[(m + i) * 36 + (tb << 2)]) = r;
        }
    }
}

#define MDN_SMEM_BYTES ((256*32 + 112*36 + 176*36) * 4)

__global__ void __launch_bounds__(256, 2)
mdn_kernel(float* __restrict__ out)
{
    extern __shared__ float sm[];
    float* hT = sm;                 // [256][32], reused as h2 [112][36]
    float* h1 = hT + 256 * 32;      // [112][36]
    float* o3 = h1 + 112 * 36;      // [176][36]

    const int tid = threadIdx.x;
    const int t   = blockIdx.x >> 3;
    const int bg  = blockIdx.x & 7;

    const float* hp = g_H + (size_t)t * 65536 + (bg << 5);
    for (int i = tid; i < 2048; i += 256) {
        int k = i >> 3, nb = i & 7;
        float4 v = *reinterpret_cast<const float4*>(hp + (size_t)k * 256 + (nb << 2));
        *reinterpret_cast<float4*>(&hT[k * 32 + (nb << 2)]) = v;
    }
    __syncthreads();

    mdn_gemm(g_W1t, 112, 28, 256, hT, 32, h1, g_b1p, true);
    __syncthreads();
    mdn_gemm(g_W2t, 112, 28, 112, h1, 36, hT, g_b2p, true);   // h2 -> hT (reuse)
    __syncthreads();
    mdn_gemm(g_W3t, 176, 44, 112, hT, 36, o3, g_b3p, false);
    __syncthreads();

    if (tid < 32) {
        int n = tid;
        size_t r = (size_t)((bg << 5) + n) * NSTEP + t;
        float l[5];
        float mx = -1e30f;
#pragma unroll
        for (int k = 0; k < 5; ++k) { l[k] = o3[k * 36 + n]; mx = fmaxf(mx, l[k]); }
        float s = 0.f;
#pragma unroll
        for (int k = 0; k < 5; ++k) { l[k] = __expf(l[k] - mx); s += l[k]; }
        float inv = 1.f / s;
#pragma unroll
        for (int k = 0; k < 5; ++k) out[r * 5 + k] = l[k] * inv;
#pragma unroll
        for (int k = 0; k < 5; ++k)
            out[VARBASE + r * 5 + k] = __expf(o3[(5 + k) * 36 + n]);
    }
    for (int i = tid; i < 5120; i += 256) {
        int n = i / 160, j = i - n * 160;
        size_t r = (size_t)((bg << 5) + n) * NSTEP + t;
        out[MEANBASE + r * 160 + j] = o3[(10 + j) * 36 + n];
    }
}

extern "C" void kernel_launch(void* const* d_in, const int* in_sizes, int n_in,
                              void* d_out, int out_size)
{
    const float* x    = (const float*)d_in[0];
    const float* W_ih = (const float*)d_in[1];
    const float* W_hh = (const float*)d_in[2];
    const float* b_ih = (const float*)d_in[3];
    const float* b_hh = (const float*)d_in[4];
    const float* W1   = (const float*)d_in[5];
    const float* b1   = (const float*)d_in[6];
    const float* W2   = (const float*)d_in[7];
    const float* b2   = (const float*)d_in[8];
    const float* W3   = (const float*)d_in[9];
    const float* b3   = (const float*)d_in[10];
    float* out = (float*)d_out;

    cudaFuncSetAttribute(lstm_kernel, cudaFuncAttributeMaxDynamicSharedMemorySize, LSTM_SMEM_BYTES);
    cudaFuncSetAttribute(mdn_kernel,  cudaFuncAttributeMaxDynamicSharedMemorySize, MDN_SMEM_BYTES);

    prep_w<<<128, 256>>>(W1, b1, W2, b2, W3, b3);
    xproj_kernel<<<dim3(NSTEP, 16, 4), 256>>>(x, W_ih);
    lstm_kernel<<<148, 512, LSTM_SMEM_BYTES>>>(W_hh, b_ih, b_hh);
    mdn_kernel<<<NSTEP * 8, 256, MDN_SMEM_BYTES>>>(out);
}

// round 17
// speedup vs baseline: 2.9383x; 1.7172x over previous
#include <cuda_runtime.h>
#include <cuda_bf16.h>
#include <cstdint>

#define TDIM   1024
#define NSTEP  1023
#define IN_DIM 35

// output layout: coeff [256][1023][5] | mean [256][1023][5][32] | var [256][1023][5]
#define MEANBASE 1309440
#define VARBASE  43211520

// ---------------- device scratch (allocation-free) ----------------
__device__ float g_H[(size_t)NSTEP * 256 * 256];            // fp32 h, [t][k][b] (MDN)
__device__ __nv_bfloat16 g_Hb[(size_t)NSTEP * 256 * 256];   // bf16 h, [t][k][b] (recurrence)
__device__ float g_GX[(size_t)NSTEP * 1024 * 256];          // x-projection [t][j][b]
__device__ float g_W1t[256 * 112];
__device__ float g_W2t[112 * 112];
__device__ float g_W3t[112 * 176];
__device__ float g_b1p[112];
__device__ float g_b2p[112];
__device__ float g_b3p[176];
__device__ unsigned g_bar[8];

// ---------------- prep ----------------
__global__ void prep_w(const float* __restrict__ W1, const float* __restrict__ b1,
                       const float* __restrict__ W2, const float* __restrict__ b2,
                       const float* __restrict__ W3, const float* __restrict__ b3)
{
    int id = blockIdx.x * blockDim.x + threadIdx.x;
    int stride = gridDim.x * blockDim.x;
    if (id < 8) g_bar[id] = 0u;
    for (int i = id; i < 256 * 112; i += stride) {
        int k = i / 112, m = i - k * 112;
        g_W1t[i] = (m < 100) ? W1[m * 256 + k] : 0.f;
    }
    for (int i = id; i < 112 * 112; i += stride) {
        int k = i / 112, m = i - k * 112;
        g_W2t[i] = (k < 100 && m < 100) ? W2[m * 100 + k] : 0.f;
    }
    for (int i = id; i < 112 * 176; i += stride) {
        int k = i / 176, m = i - k * 176;
        g_W3t[i] = (k < 100 && m < 170) ? W3[m * 100 + k] : 0.f;
    }
    for (int i = id; i < 112; i += stride) {
        g_b1p[i] = (i < 100) ? b1[i] : 0.f;
        g_b2p[i] = (i < 100) ? b2[i] : 0.f;
    }
    for (int i = id; i < 176; i += stride) g_b3p[i] = (i < 170) ? b3[i] : 0.f;
}

// ---------------- x-projection ----------------
__global__ void __launch_bounds__(256)
xproj_kernel(const float* __restrict__ x, const float* __restrict__ W_ih)
{
    __shared__ float Ws[IN_DIM][64];
    __shared__ float xs[IN_DIM][64];
    const int tid = threadIdx.x;
    const int t  = blockIdx.x;
    const int jt = blockIdx.y;
    const int bt = blockIdx.z;

    for (int i = tid; i < 64 * IN_DIM; i += 256) {
        int m = i / IN_DIM, c = i - m * IN_DIM;
        Ws[c][m] = W_ih[(jt * 64 + m) * IN_DIM + c];
    }
    for (int i = tid; i < 64 * IN_DIM; i += 256) {
        int n = i / IN_DIM, c = i - n * IN_DIM;
        xs[c][n] = x[((size_t)(bt * 64 + n) * TDIM + t) * IN_DIM + c];
    }
    __syncthreads();

    const int tm = tid >> 4;
    const int tb = tid & 15;
    float acc[4][4];
#pragma unroll
    for (int i = 0; i < 4; ++i)
#pragma unroll
        for (int j = 0; j < 4; ++j) acc[i][j] = 0.f;
#pragma unroll 5
    for (int c = 0; c < IN_DIM; ++c) {
        float4 a  = *reinterpret_cast<const float4*>(&Ws[c][tm << 2]);
        float4 b4 = *reinterpret_cast<const float4*>(&xs[c][tb << 2]);
        float av[4] = {a.x, a.y, a.z, a.w};
        float bv[4] = {b4.x, b4.y, b4.z, b4.w};
#pragma unroll
        for (int i = 0; i < 4; ++i)
#pragma unroll
            for (int j = 0; j < 4; ++j) acc[i][j] = fmaf(av[i], bv[j], acc[i][j]);
    }
    float* dst = g_GX + (size_t)t * 262144 + (size_t)(jt * 64 + (tm << 2)) * 256
                 + bt * 64 + (tb << 2);
#pragma unroll
    for (int i = 0; i < 4; ++i)
        *reinterpret_cast<float4*>(dst + (size_t)i * 256) =
            make_float4(acc[i][0], acc[i][1], acc[i][2], acc[i][3]);
}

__device__ __forceinline__ float sigf(float v)     { return 1.f / (1.f + __expf(-v)); }
__device__ __forceinline__ float tanhfast(float v) { return 1.f - 2.f / (__expf(2.f * v) + 1.f); }
__device__ __forceinline__ float ldcg1(const float* p) {
    float v;
    asm volatile("ld.global.cg.f32 %0,[%1];" : "=f"(v) : "l"(p));
    return v;
}
__device__ __forceinline__ uint2 ldcg2u(const void* p) {
    uint2 v;
    asm volatile("ld.global.cg.v2.u32 {%0,%1},[%2];" : "=r"(v.x), "=r"(v.y) : "l"(p));
    return v;
}
__device__ __forceinline__ uint32_t smem_u32(const void* p) {
    uint32_t a;
    asm("{ .reg .u64 t; cvta.to.shared.u64 t, %1; cvt.u32.u64 %0, t; }" : "=r"(a) : "l"(p));
    return a;
}

// ---------------- mma helpers ----------------
__device__ __forceinline__ void ldsm4(uint32_t* r, uint32_t a) {
    asm volatile("ldmatrix.sync.aligned.m8n8.x4.shared.b16 {%0,%1,%2,%3}, [%4];"
        : "=r"(r[0]), "=r"(r[1]), "=r"(r[2]), "=r"(r[3]) : "r"(a));
}
__device__ __forceinline__ void ldsm2t(uint32_t* r, uint32_t a) {
    asm volatile("ldmatrix.sync.aligned.m8n8.x2.trans.shared.b16 {%0,%1}, [%2];"
        : "=r"(r[0]), "=r"(r[1]) : "r"(a));
}
__device__ __forceinline__ void mma_bf16(float* d, const uint32_t* a, const uint32_t* b) {
    asm volatile("mma.sync.aligned.m16n8k16.row.col.f32.bf16.bf16.f32 "
        "{%0,%1,%2,%3}, {%4,%5,%6,%7}, {%8,%9}, {%0,%1,%2,%3};"
        : "+f"(d[0]), "+f"(d[1]), "+f"(d[2]), "+f"(d[3])
        : "r"(a[0]), "r"(a[1]), "r"(a[2]), "r"(a[3]), "r"(b[0]), "r"(b[1]));
}
__device__ __forceinline__ uint32_t pack_bf(__nv_bfloat16 lo, __nv_bfloat16 hi) {
    return (uint32_t)__bfloat16_as_ushort(lo) | ((uint32_t)__bfloat16_as_ushort(hi) << 16);
}

// ---------------- persistent LSTM (HMMA, single bf16 product, counter barrier) ----------------
// grid 148 (>=128 exit): jg = blockIdx>>3 (16 hid-tiles of 16), bg = blockIdx&7 (8 batch-tiles of 32)
// M=64 gate rows (m = jh*4 + gate), N=32, K=256. 512 threads = 16 warps (4 mt x 4 nt).
#define WSP_OFF  0                    // bf16 [m=64][k pad 264]
#define HSP_OFF  33792                // bf16 [k=256][n pad 40]
#define WGS_OFF  54272                // per-warp f32 [16][10] (640B each)
#define LSTM_SMEM_BYTES 120000        // padded: force 1 block/SM

__global__ void __launch_bounds__(512, 1)
lstm_kernel(const float* __restrict__ W_hh,
            const float* __restrict__ b_ih, const float* __restrict__ b_hh)
{
    extern __shared__ char smc[];
    if (blockIdx.x >= 128) return;
    const uint32_t sbase = smem_u32(smc);

    const int tid = threadIdx.x;
    const int bg  = blockIdx.x & 7;
    const int jg  = blockIdx.x >> 3;

    // one-time W staging: m = jh*4 + gate, single bf16, [m=64][k pad 264]
    {
        int m = tid >> 3, kc = tid & 7;
        int j = (m & 3) * 256 + (jg << 4) + (m >> 2);      // gate*256 + jh_full
        const float* wrow = W_hh + (size_t)j * 256;
#pragma unroll
        for (int q = 0; q < 4; ++q) {
            int k0 = kc * 32 + q * 8;
            float4 u0 = *reinterpret_cast<const float4*>(wrow + k0);
            float4 u1 = *reinterpret_cast<const float4*>(wrow + k0 + 4);
            uint4 qa = make_uint4(
                pack_bf(__float2bfloat16(u0.x), __float2bfloat16(u0.y)),
                pack_bf(__float2bfloat16(u0.z), __float2bfloat16(u0.w)),
                pack_bf(__float2bfloat16(u1.x), __float2bfloat16(u1.y)),
                pack_bf(__float2bfloat16(u1.z), __float2bfloat16(u1.w)));
            *reinterpret_cast<uint4*>(smc + WSP_OFF + m * 528 + k0 * 2) = qa;
        }
    }
    __syncthreads();

    // roles
    const int wid  = tid >> 5;
    const int lane = tid & 31;
    const int mt = wid >> 2, nt = wid & 3;
    const uint32_t aA0 = sbase + WSP_OFF +
        (uint32_t)(mt * 16 + (lane & 15)) * 528 + ((lane >> 4) * 16);
    const uint32_t aB0 = sbase + HSP_OFF + (uint32_t)(lane & 15) * 80 + nt * 16;
    float* wg = reinterpret_cast<float*>(smc + WGS_OFF + wid * 640);

    // combine cell: jh_full = jg*16 + mt*4 + jhl ; b = bg*32 + nt*8 + nl
    const int jhl = lane >> 3, nl = lane & 7;
    const int jh_full = (jg << 4) + mt * 4 + jhl;
    const int bcol = (bg << 5) + nt * 8 + nl;
    const size_t gxoff = (size_t)jh_full * 256 + bcol;
    const size_t hoff  = (size_t)jh_full * 256 + bcol;

    float bias_r[4];
#pragma unroll
    for (int g = 0; g < 4; ++g) {
        int j = g * 256 + jh_full;
        bias_r[g] = b_ih[j] + b_hh[j];
    }
    float creg = 0.f;

    // staging role
    const int sn4 = (tid & 7) << 2;
    const int skb = tid >> 3;

    for (int t = 0; t < NSTEP; ++t) {
        // early gx loads
        const float* gp = g_GX + (size_t)t * 262144 + gxoff;
        float gxi = ldcg1(gp);
        float gxf = ldcg1(gp + 65536);
        float gxg = ldcg1(gp + 131072);
        float gxo = ldcg1(gp + 196608);

        // stage h(t-1): bf16 copy g_Hb -> smem [k][n pad 40]
        if (t > 0) {
            const __nv_bfloat16* hb = g_Hb + (size_t)(t - 1) * 65536 + (bg << 5) + sn4;
#pragma unroll
            for (int i = 0; i < 4; ++i) {
                int k = skb + (i << 6);
                uint2 v = ldcg2u(hb + (size_t)k * 256);
                *reinterpret_cast<uint2*>(smc + HSP_OFF + k * 80 + sn4 * 2) = v;
            }
        }
        __syncthreads();

        // tensor GEMM (single product) + in-warp combine
        float gi = 0.f, gf = 0.f, gg = 0.f, go = 0.f;
        if (t > 0) {
            float d[4] = {0.f, 0.f, 0.f, 0.f};
#pragma unroll
            for (int kk = 0; kk < 16; ++kk) {
                uint32_t a0[4], b0[2];
                ldsm4(a0, aA0 + kk * 32);
                ldsm2t(b0, aB0 + kk * 1280);
                mma_bf16(d, a0, b0);
            }
            int r0 = lane >> 2, c2 = (lane & 3) << 1;
            *reinterpret_cast<float2*>(wg + r0 * 10 + c2) = make_float2(d[0], d[1]);
            *reinterpret_cast<float2*>(wg + (r0 + 8) * 10 + c2) = make_float2(d[2], d[3]);
            __syncwarp();
            gi = wg[(jhl * 4 + 0) * 10 + nl];
            gf = wg[(jhl * 4 + 1) * 10 + nl];
            gg = wg[(jhl * 4 + 2) * 10 + nl];
            go = wg[(jhl * 4 + 3) * 10 + nl];
        }
        // combine (c in register)
        {
            float iv = sigf(gxi + bias_r[0] + gi);
            float fv = sigf(gxf + bias_r[1] + gf);
            float gv = tanhfast(gxg + bias_r[2] + gg);
            float ov = sigf(gxo + bias_r[3] + go);
            float cv = fv * creg + iv * gv;
            creg = cv;
            float hv = ov * tanhfast(cv);
            g_H [(size_t)t * 65536 + hoff] = hv;
            g_Hb[(size_t)t * 65536 + hoff] = __float2bfloat16(hv);
        }
        __syncthreads();

        // inter-block barrier (16 jg-blocks sharing this bg): one atomic, one poller
        if (tid == 0) {
            __threadfence();
            asm volatile("red.release.gpu.global.add.u32 [%0],%1;"
                         :: "l"(&g_bar[bg]), "r"(1u) : "memory");
            unsigned target = (unsigned)(t + 1) << 4;
            unsigned v;
            for (;;) {
                asm volatile("ld.acquire.gpu.global.u32 %0,[%1];"
                             : "=r"(v) : "l"(&g_bar[bg]));
                if (v >= target) break;
                __nanosleep(32);
            }
        }
        __syncthreads();
    }
}

// ---------------- MDN head ----------------
__device__ __forceinline__ void mdn_gemm(
    const float* __restrict__ At, int ldA, int mTiles, int K,
    const float* __restrict__ Bs, int ldb, float* __restrict__ Cs,
    const float* __restrict__ biasv, bool relu)
{
    for (int tile = threadIdx.x; tile < mTiles * 8; tile += blockDim.x) {
        int tm = tile % mTiles, tb = tile / mTiles;
        int m = tm << 2;
        const float* Ap = At + m;
        const float* Bp = Bs + (tb << 2);
        float acc[4][4];
#pragma unroll
        for (int i = 0; i < 4; ++i)
#pragma unroll
            for (int j = 0; j < 4; ++j) acc[i][j] = 0.f;
#pragma unroll 8
        for (int k = 0; k < K; ++k) {
            float4 a  = *reinterpret_cast<const float4*>(Ap + k * ldA);
            float4 b4 = *reinterpret_cast<const float4*>(Bp + k * ldb);
            float av[4] = {a.x, a.y, a.z, a.w};
            float bv[4] = {b4.x, b4.y, b4.z, b4.w};
#pragma unroll
            for (int i = 0; i < 4; ++i)
#pragma unroll
                for (int j = 0; j < 4; ++j) acc[i][j] = fmaf(av[i], bv[j], acc[i][j]);
        }
#pragma unroll
        for (int i = 0; i < 4; ++i) {
            float bv = biasv[m + i];
            float4 r = make_float4(acc[i][0] + bv, acc[i][1] + bv,
                                   acc[i][2] + bv, acc[i][3] + bv);
            if (relu) { r.x = fmaxf(r.x, 0.f); r.y = fmaxf(r.y, 0.f);
                        r.z = fmaxf(r.z, 0.f); r.w = fmaxf(r.w, 0.f); }
            *reinterpret_cast<float4*>(&Cs[(m + i) * 36 + (tb << 2)]) = r;
        }
    }
}

#define MDN_SMEM_BYTES ((256*32 + 112*36 + 176*36) * 4)

__global__ void __launch_bounds__(256, 2)
mdn_kernel(float* __restrict__ out)
{
    extern __shared__ float sm[];
    float* hT = sm;                 // [256][32], reused as h2 [112][36]
    float* h1 = hT + 256 * 32;      // [112][36]
    float* o3 = h1 + 112 * 36;      // [176][36]

    const int tid = threadIdx.x;
    const int t   = blockIdx.x >> 3;
    const int bg  = blockIdx.x & 7;

    const float* hp = g_H + (size_t)t * 65536 + (bg << 5);
    for (int i = tid; i < 2048; i += 256) {
        int k = i >> 3, nb = i & 7;
        float4 v = *reinterpret_cast<const float4*>(hp + (size_t)k * 256 + (nb << 2));
        *reinterpret_cast<float4*>(&hT[k * 32 + (nb << 2)]) = v;
    }
    __syncthreads();

    mdn_gemm(g_W1t, 112, 28, 256, hT, 32, h1, g_b1p, true);
    __syncthreads();
    mdn_gemm(g_W2t, 112, 28, 112, h1, 36, hT, g_b2p, true);   // h2 -> hT (reuse)
    __syncthreads();
    mdn_gemm(g_W3t, 176, 44, 112, hT, 36, o3, g_b3p, false);
    __syncthreads();

    if (tid < 32) {
        int n = tid;
        size_t r = (size_t)((bg << 5) + n) * NSTEP + t;
        float l[5];
        float mx = -1e30f;
#pragma unroll
        for (int k = 0; k < 5; ++k) { l[k] = o3[k * 36 + n]; mx = fmaxf(mx, l[k]); }
        float s = 0.f;
#pragma unroll
        for (int k = 0; k < 5; ++k) { l[k] = __expf(l[k] - mx); s += l[k]; }
        float inv = 1.f / s;
#pragma unroll
        for (int k = 0; k < 5; ++k) out[r * 5 + k] = l[k] * inv;
#pragma unroll
        for (int k = 0; k < 5; ++k)
            out[VARBASE + r * 5 + k] = __expf(o3[(5 + k) * 36 + n]);
    }
    for (int i = tid; i < 5120; i += 256) {
        int n = i / 160, j = i - n * 160;
        size_t r = (size_t)((bg << 5) + n) * NSTEP + t;
        out[MEANBASE + r * 160 + j] = o3[(10 + j) * 36 + n];
    }
}

extern "C" void kernel_launch(void* const* d_in, const int* in_sizes, int n_in,
                              void* d_out, int out_size)
{
    const float* x    = (const float*)d_in[0];
    const float* W_ih = (const float*)d_in[1];
    const float* W_hh = (const float*)d_in[2];
    const float* b_ih = (const float*)d_in[3];
    const float* b_hh = (const float*)d_in[4];
    const float* W1   = (const float*)d_in[5];
    const float* b1   = (const float*)d_in[6];
    const float* W2   = (const float*)d_in[7];
    const float* b2   = (const float*)d_in[8];
    const float* W3   = (const float*)d_in[9];
    const float* b3   = (const float*)d_in[10];
    float* out = (float*)d_out;

    cudaFuncSetAttribute(lstm_kernel, cudaFuncAttributeMaxDynamicSharedMemorySize, LSTM_SMEM_BYTES);
    cudaFuncSetAttribute(mdn_kernel,  cudaFuncAttributeMaxDynamicSharedMemorySize, MDN_SMEM_BYTES);

    prep_w<<<128, 256>>>(W1, b1, W2, b2, W3, b3);
    xproj_kernel<<<dim3(NSTEP, 16, 4), 256>>>(x, W_ih);
    lstm_kernel<<<148, 512, LSTM_SMEM_BYTES>>>(W_hh, b_ih, b_hh);
    mdn_kernel<<<NSTEP * 8, 256, MDN_SMEM_BYTES>>>(out);
}